// round 14
// baseline (speedup 1.0000x reference)
#include <cuda_runtime.h>
#include <cuda_fp16.h>
#include <cstdint>

// ---------------------------------------------------------------------------
// QuadraticAttentionModule via fp16 mma.sync.m16n8k16.
//   out[b,o] = bias[o] + sum_k X[b,k] * W[o,k]
//   X[b,k] = xf[b,k] (k<1024) else xf[b,i]*xf[b,j]
// GEMM: M=o(1024), N=b(64), K=525824. X pre-materialized as fp16.
// R14 = R13 (proven schedule, __ldcs W) + prefetch.global.L2 of stage s+2's
// W tile: mainloop LDGs become L2 hits, collapsing the storeW tail stall.
// ---------------------------------------------------------------------------

#define IN_DIM 1024
#define NB     64
#define NOUT   1024
#define KTOT   525824
#define KT     64
#define STAGES (KTOT / KT)       // 8216
#define KS     38                // 8*38 = 304 CTAs = 2/SM
#define MT     8
#define SPLIT_Q (STAGES / KS)    // 216
#define SPLIT_R (STAGES % KS)    // 8

#define WSTR     72              // halves per smem row (64 + 8 pad), 144B
#define W_TILE_H (128 * WSTR)    // 18432 B
#define X_TILE_H (64 * WSTR)     //  9216 B
#define STAGE_B  ((W_TILE_H + X_TILE_H) * 2)   // 27648 B
#define SMEM_BYTES (2 * STAGE_B)               // 55296 B

// Scratch (__device__ globals per allocation rules)
__device__ int    d_ij[KTOT];
__device__ __align__(16) __half d_Xh[(size_t)NB * KTOT];   // [b][k] fp16 RN
__device__ float  d_partial[(size_t)KS * NOUT * NB];       // [split][o][b]

// --------------------------- PTX helpers ------------------------------------

__device__ __forceinline__ uint32_t smem_u32(const void* p) {
    uint32_t a;
    asm("{ .reg .u64 t; cvta.to.shared.u64 t, %1; cvt.u32.u64 %0, t; }" : "=r"(a) : "l"(p));
    return a;
}
__device__ __forceinline__ void cp16(uint32_t saddr, const void* gptr) {
    asm volatile("cp.async.cg.shared.global [%0], [%1], 16;"
                 :: "r"(saddr), "l"(gptr) : "memory");
}
__device__ __forceinline__ void ldsm4(uint32_t* r, uint32_t addr) {
    asm volatile("ldmatrix.sync.aligned.m8n8.x4.shared.b16 {%0,%1,%2,%3}, [%4];"
                 : "=r"(r[0]), "=r"(r[1]), "=r"(r[2]), "=r"(r[3]) : "r"(addr));
}
__device__ __forceinline__ void mma16816(float* d, const uint32_t* a, const uint32_t* b) {
    asm volatile(
        "mma.sync.aligned.m16n8k16.row.col.f32.f16.f16.f32 "
        "{%0,%1,%2,%3}, {%4,%5,%6,%7}, {%8,%9}, {%0,%1,%2,%3};\n"
        : "+f"(d[0]), "+f"(d[1]), "+f"(d[2]), "+f"(d[3])
        : "r"(a[0]), "r"(a[1]), "r"(a[2]), "r"(a[3]), "r"(b[0]), "r"(b[1]));
}
// Pack two fp32 -> one u32 of two rn-rounded fp16 (lo = a, hi = b).
__device__ __forceinline__ uint32_t packh2(float a, float b) {
    uint32_t r;
    asm("cvt.rn.f16x2.f32 %0, %2, %1;" : "=r"(r) : "f"(a), "f"(b));
    return r;
}
// Streaming (evict-first) 16B load for the zero-reuse W operand.
__device__ __forceinline__ float4 ldg_cs4(const float4* p) {
    float4 v;
    asm volatile("ld.global.cs.v4.f32 {%0,%1,%2,%3}, [%4];"
                 : "=f"(v.x), "=f"(v.y), "=f"(v.z), "=f"(v.w) : "l"(p));
    return v;
}
__device__ __forceinline__ void pf_l2(const void* p) {
    asm volatile("prefetch.global.L2 [%0];" :: "l"(p));
}

// --------------------------- prep kernels ----------------------------------

__device__ __forceinline__ long long triu_off(long long i) {
    return i * IN_DIM - i * (i - 1) / 2;
}

__global__ void qa_ij() {
    int k = blockIdx.x * blockDim.x + threadIdx.x;
    if (k >= KTOT) return;
    if (k < IN_DIM) { d_ij[k] = (k << 16) | 0xFFFF; return; }
    long long p = k - IN_DIM;
    double nn = 2.0 * IN_DIM + 1.0;
    int i = (int)((nn - sqrt(nn * nn - 8.0 * (double)p)) * 0.5);
    if (i < 0) i = 0;
    if (i > IN_DIM - 1) i = IN_DIM - 1;
    while (i > 0 && triu_off(i) > p) --i;
    while (i < IN_DIM - 1 && triu_off(i + 1) <= p) ++i;
    int j = i + (int)(p - triu_off(i));
    d_ij[k] = (i << 16) | j;
}

// Materialize X[b][k] in fp16 (round-to-nearest).
__global__ void qa_buildXh(const float* __restrict__ in) {
    int k = blockIdx.x * 256 + threadIdx.x;    // grid.x = KTOT/256 = 2054
    int b = blockIdx.y;
    int ij = d_ij[k];
    int i = ij >> 16, j = ij & 0xFFFF;
    float v = in[b * IN_DIM + i];
    if (j != 0xFFFF) v *= in[b * IN_DIM + j];
    d_Xh[(size_t)b * KTOT + k] = __float2half_rn(v);
}

// --------------------------- main GEMM -------------------------------------
// CTA tile 128(M) x 64(N) x KT=64. 8 warps as 2(M,64) x 4(N,16).
// Per slot: W [128][72] halves, X [64][72] halves (rows padded to 144B).

__global__ __launch_bounds__(256, 2)
void qa_main(const float* __restrict__ W) {
    extern __shared__ __align__(128) char smem[];
    const uint32_t sb = smem_u32(smem);
    const int tid = threadIdx.x, lane = tid & 31, wid = tid >> 5;
    const int warpM = wid >> 2, warpN = wid & 3;

    const int o_base = blockIdx.x * 128;
    const int split  = blockIdx.y;
    const int s0 = split * SPLIT_Q + min(split, SPLIT_R);
    const int s1 = s0 + SPLIT_Q + (split < SPLIT_R ? 1 : 0);

    // --- W producer: step j -> row (tid>>4)+16j, 16B chunk tid&15 (coalesced).
    const int wr0 = tid >> 4, wc = tid & 15;
    const float* wptr = W + (size_t)(o_base + wr0) * KTOT + (size_t)s0 * KT + wc * 4;
    const uint32_t wsto = wr0 * 144 + wc * 8;          // fp16 dst (+j*16*144)

    // --- W prefetch: thread t -> row t>>1, 128B line t&1 (256 lines = tile).
    const float* pfptr = W + (size_t)(o_base + (tid >> 1)) * KTOT
                           + (size_t)s0 * KT + (tid & 1) * 32;

    // --- X producer: step j -> row (tid>>3)+32j, 16B chunk tid&7.
    const int xr0 = tid >> 3, xc = tid & 7;
    const __half* xptr = d_Xh + (size_t)xr0 * KTOT + (size_t)s0 * KT + xc * 8;
    const uint32_t xsto = xr0 * 144 + xc * 16;         // (+j*32*144)

    // Fragment base byte offsets within slot (ldmatrix address schemes)
    const uint32_t aoff = ((warpM * 64 + (lane & 15)) * WSTR + ((lane >> 4) * 8)) * 2;
    const uint32_t boff = ((warpN * 16 + ((lane >> 4) * 8) + (lane & 7)) * WSTR
                          + (((lane >> 3) & 1) * 8)) * 2;

    float4 wreg[8];
    float  acc[4][2][4];
    #pragma unroll
    for (int mt = 0; mt < 4; mt++)
        #pragma unroll
        for (int nt = 0; nt < 2; nt++)
            #pragma unroll
            for (int r = 0; r < 4; r++) acc[mt][nt][r] = 0.f;

    auto loadW = [&](int s) {
        const float* p = wptr + (size_t)(s - s0) * KT;
        #pragma unroll
        for (int j = 0; j < 8; j++)
            wreg[j] = ldg_cs4((const float4*)(p + (size_t)(16 * j) * KTOT));
    };
    auto cpX = [&](int s, int slot) {
        uint32_t dst = sb + slot * STAGE_B + W_TILE_H * 2 + xsto;
        const __half* p = xptr + (size_t)(s - s0) * KT;
        cp16(dst,            p);
        cp16(dst + 32 * 144, p + (size_t)32 * KTOT);
        asm volatile("cp.async.commit_group;" ::: "memory");
    };
    auto storeW = [&](int slot) {
        char* base = smem + slot * STAGE_B + wsto;
        #pragma unroll
        for (int j = 0; j < 8; j++) {
            uint2 u;
            u.x = packh2(wreg[j].x, wreg[j].y);
            u.y = packh2(wreg[j].z, wreg[j].w);
            *(uint2*)(base + j * 16 * 144) = u;        // STS.64, 2-phase clean
        }
    };
    auto compute = [&](int slot) {
        const uint32_t wbase = sb + slot * STAGE_B;
        const uint32_t xbase = wbase + W_TILE_H * 2;
        #pragma unroll
        for (int kk = 0; kk < KT; kk += 16) {
            uint32_t a[4][4], b4[4];
            #pragma unroll
            for (int mt = 0; mt < 4; mt++)
                ldsm4(a[mt], wbase + aoff + (mt * 16 * WSTR + kk) * 2);
            ldsm4(b4, xbase + boff + kk * 2);
            #pragma unroll
            for (int mt = 0; mt < 4; mt++)
                #pragma unroll
                for (int nt = 0; nt < 2; nt++)
                    mma16816(acc[mt][nt], a[mt], b4 + nt * 2);
        }
    };

    // Prologue (also warm L2 for s0+1)
    loadW(s0);
    cpX(s0, 0);
    if (s0 + 1 < s1) pf_l2(pfptr + (size_t)1 * KT);
    storeW(0);
    asm volatile("cp.async.wait_group 0;" ::: "memory");
    __syncthreads();

    for (int s = s0; s < s1; s++) {
        const int cur = (s - s0) & 1, nxt = cur ^ 1;
        const bool more = (s + 1 < s1);
        if (more) { loadW(s + 1); cpX(s + 1, nxt); }   // gmem in flight under MMAs
        if (s + 2 < s1) pf_l2(pfptr + (size_t)(s + 2 - s0) * KT);  // warm L2
        compute(cur);
        if (more) storeW(nxt);
        asm volatile("cp.async.wait_group 0;" ::: "memory");
        __syncthreads();
    }

    // Epilogue: partial[split][o][b], vectorized float2
    float* part = d_partial + (size_t)split * (NOUT * NB);
    #pragma unroll
    for (int mt = 0; mt < 4; mt++)
        #pragma unroll
        for (int nt = 0; nt < 2; nt++) {
            int o  = o_base + warpM * 64 + mt * 16 + (lane >> 2);
            int bb = warpN * 16 + nt * 8 + 2 * (lane & 3);
            *(float2*)&part[(size_t)o * NB + bb] =
                make_float2(acc[mt][nt][0], acc[mt][nt][1]);
            *(float2*)&part[(size_t)(o + 8) * NB + bb] =
                make_float2(acc[mt][nt][2], acc[mt][nt][3]);
        }
}

// --------------------------- reduce ----------------------------------------

__global__ void qa_reduce(const float* __restrict__ bias, float* __restrict__ out) {
    int t = blockIdx.x * blockDim.x + threadIdx.x;  // t = o*64 + b
    int o = t >> 6, b = t & 63;
    float s = bias[o];
    #pragma unroll
    for (int k = 0; k < KS; k++)
        s += d_partial[(size_t)k * (NOUT * NB) + t];   // coalesced reads
    out[(size_t)b * NOUT + o] = s;                     // scattered 4B writes
}

// --------------------------- launch ----------------------------------------

extern "C" void kernel_launch(void* const* d_in, const int* in_sizes, int n_in,
                              void* d_out, int out_size) {
    const float* input_ = (const float*)d_in[0];   // (64,32,32) fp32
    const float* W      = (const float*)d_in[1];   // (1024, 525824) fp32
    const float* bias   = (const float*)d_in[2];   // (1024,) fp32
    float* out = (float*)d_out;                    // (64,32,32) fp32

    cudaFuncSetAttribute(qa_main, cudaFuncAttributeMaxDynamicSharedMemorySize, SMEM_BYTES);

    qa_ij<<<(KTOT + 1023) / 1024, 1024>>>();
    qa_buildXh<<<dim3(KTOT / 256, NB), 256>>>(input_);
    qa_main<<<dim3(MT, KS), 256, SMEM_BYTES>>>(W);
    qa_reduce<<<64, 1024>>>(bias, out);
}

// round 15
// speedup vs baseline: 1.0545x; 1.0545x over previous
#include <cuda_runtime.h>
#include <cuda_fp16.h>
#include <cstdint>

// ---------------------------------------------------------------------------
// QuadraticAttentionModule via fp16 mma.sync.m16n8k16.
//   out[b,o] = bias[o] + sum_k X[b,k] * W[o,k]
//   X[b,k] = xf[b,k] (k<1024) else xf[b,i]*xf[b,j]
// GEMM: M=o(1024), N=b(64), K=525824. X pre-materialized as fp16.
// R15 = R13 stage schedule, CTA tile 64(M)x64(N), 128 threads, 4 CTAs/SM
// (grid 16x38 = 608 = 4*152): 4 independent pipelines per SM hide each
// other's barrier tails. Per-thread work identical to R13.
// ---------------------------------------------------------------------------

#define IN_DIM 1024
#define NB     64
#define NOUT   1024
#define KTOT   525824
#define KT     64
#define STAGES (KTOT / KT)       // 8216
#define KS     38                // 16*38 = 608 CTAs = 4/SM
#define MT     16                // M tiles of 64
#define SPLIT_Q (STAGES / KS)    // 216
#define SPLIT_R (STAGES % KS)    // 8

#define WSTR     72              // halves per smem row (64 + 8 pad), 144B
#define W_TILE_B (64 * WSTR * 2)    // 9216 B
#define X_TILE_B (64 * WSTR * 2)    // 9216 B
#define STAGE_B  (W_TILE_B + X_TILE_B)   // 18432 B
#define SMEM_BYTES (2 * STAGE_B)         // 36864 B (x4 CTA = 147456)

// Scratch (__device__ globals per allocation rules)
__device__ int    d_ij[KTOT];
__device__ __align__(16) __half d_Xh[(size_t)NB * KTOT];   // [b][k] fp16 RN
__device__ float  d_partial[(size_t)KS * NOUT * NB];       // [split][o][b]

// --------------------------- PTX helpers ------------------------------------

__device__ __forceinline__ uint32_t smem_u32(const void* p) {
    uint32_t a;
    asm("{ .reg .u64 t; cvta.to.shared.u64 t, %1; cvt.u32.u64 %0, t; }" : "=r"(a) : "l"(p));
    return a;
}
__device__ __forceinline__ void cp16(uint32_t saddr, const void* gptr) {
    asm volatile("cp.async.cg.shared.global [%0], [%1], 16;"
                 :: "r"(saddr), "l"(gptr) : "memory");
}
__device__ __forceinline__ void ldsm4(uint32_t* r, uint32_t addr) {
    asm volatile("ldmatrix.sync.aligned.m8n8.x4.shared.b16 {%0,%1,%2,%3}, [%4];"
                 : "=r"(r[0]), "=r"(r[1]), "=r"(r[2]), "=r"(r[3]) : "r"(addr));
}
__device__ __forceinline__ void mma16816(float* d, const uint32_t* a, const uint32_t* b) {
    asm volatile(
        "mma.sync.aligned.m16n8k16.row.col.f32.f16.f16.f32 "
        "{%0,%1,%2,%3}, {%4,%5,%6,%7}, {%8,%9}, {%0,%1,%2,%3};\n"
        : "+f"(d[0]), "+f"(d[1]), "+f"(d[2]), "+f"(d[3])
        : "r"(a[0]), "r"(a[1]), "r"(a[2]), "r"(a[3]), "r"(b[0]), "r"(b[1]));
}
// Pack two fp32 -> one u32 of two rn-rounded fp16 (lo = a, hi = b).
__device__ __forceinline__ uint32_t packh2(float a, float b) {
    uint32_t r;
    asm("cvt.rn.f16x2.f32 %0, %2, %1;" : "=r"(r) : "f"(a), "f"(b));
    return r;
}
// Streaming (evict-first) 16B load for the zero-reuse W operand.
__device__ __forceinline__ float4 ldg_cs4(const float4* p) {
    float4 v;
    asm volatile("ld.global.cs.v4.f32 {%0,%1,%2,%3}, [%4];"
                 : "=f"(v.x), "=f"(v.y), "=f"(v.z), "=f"(v.w) : "l"(p));
    return v;
}

// --------------------------- prep kernels ----------------------------------

__device__ __forceinline__ long long triu_off(long long i) {
    return i * IN_DIM - i * (i - 1) / 2;
}

__global__ void qa_ij() {
    int k = blockIdx.x * blockDim.x + threadIdx.x;
    if (k >= KTOT) return;
    if (k < IN_DIM) { d_ij[k] = (k << 16) | 0xFFFF; return; }
    long long p = k - IN_DIM;
    double nn = 2.0 * IN_DIM + 1.0;
    int i = (int)((nn - sqrt(nn * nn - 8.0 * (double)p)) * 0.5);
    if (i < 0) i = 0;
    if (i > IN_DIM - 1) i = IN_DIM - 1;
    while (i > 0 && triu_off(i) > p) --i;
    while (i < IN_DIM - 1 && triu_off(i + 1) <= p) ++i;
    int j = i + (int)(p - triu_off(i));
    d_ij[k] = (i << 16) | j;
}

// Materialize X[b][k] in fp16 (round-to-nearest).
__global__ void qa_buildXh(const float* __restrict__ in) {
    int k = blockIdx.x * 256 + threadIdx.x;    // grid.x = KTOT/256 = 2054
    int b = blockIdx.y;
    int ij = d_ij[k];
    int i = ij >> 16, j = ij & 0xFFFF;
    float v = in[b * IN_DIM + i];
    if (j != 0xFFFF) v *= in[b * IN_DIM + j];
    d_Xh[(size_t)b * KTOT + k] = __float2half_rn(v);
}

// --------------------------- main GEMM -------------------------------------
// CTA tile 64(M) x 64(N) x KT=64. 4 warps as 2(M,32) x 2(N,32).
// Per slot: W [64][72] halves, X [64][72] halves (rows padded to 144B).

__global__ __launch_bounds__(128, 4)
void qa_main(const float* __restrict__ W) {
    extern __shared__ __align__(128) char smem[];
    const uint32_t sb = smem_u32(smem);
    const int tid = threadIdx.x, lane = tid & 31, wid = tid >> 5;
    const int warpM = wid >> 1, warpN = wid & 1;

    const int o_base = blockIdx.x * 64;
    const int split  = blockIdx.y;
    const int s0 = split * SPLIT_Q + min(split, SPLIT_R);
    const int s1 = s0 + SPLIT_Q + (split < SPLIT_R ? 1 : 0);

    // --- W producer: step j=0..7 -> row (tid>>4)+8j, 16B chunk tid&15.
    // 16 lanes span one 256B row: warp = 2 rows = 4 full lines, coalesced.
    const int wr0 = tid >> 4, wc = tid & 15;
    const float* wptr = W + (size_t)(o_base + wr0) * KTOT + (size_t)s0 * KT + wc * 4;
    const uint32_t wsto = wr0 * 144 + wc * 8;          // fp16 dst (+j*8*144)

    // --- X producer: step j=0..3 -> row (tid>>3)+16j, 16B chunk tid&7.
    const int xr0 = tid >> 3, xc = tid & 7;
    const __half* xptr = d_Xh + (size_t)xr0 * KTOT + (size_t)s0 * KT + xc * 8;
    const uint32_t xsto = xr0 * 144 + xc * 16;         // (+j*16*144)

    // Fragment base byte offsets within slot (ldmatrix address schemes)
    const uint32_t aoff = ((warpM * 32 + (lane & 15)) * WSTR + ((lane >> 4) * 8)) * 2;
    const uint32_t boff = ((warpN * 32 + ((lane >> 4) * 8) + (lane & 7)) * WSTR
                          + (((lane >> 3) & 1) * 8)) * 2;

    float4 wreg[8];
    float  acc[2][4][4];
    #pragma unroll
    for (int mt = 0; mt < 2; mt++)
        #pragma unroll
        for (int nt = 0; nt < 4; nt++)
            #pragma unroll
            for (int r = 0; r < 4; r++) acc[mt][nt][r] = 0.f;

    auto loadW = [&](int s) {
        const float* p = wptr + (size_t)(s - s0) * KT;
        #pragma unroll
        for (int j = 0; j < 8; j++)
            wreg[j] = ldg_cs4((const float4*)(p + (size_t)(8 * j) * KTOT));
    };
    auto cpX = [&](int s, int slot) {
        uint32_t dst = sb + slot * STAGE_B + W_TILE_B + xsto;
        const __half* p = xptr + (size_t)(s - s0) * KT;
        #pragma unroll
        for (int j = 0; j < 4; j++)
            cp16(dst + j * 16 * 144, p + (size_t)(16 * j) * KTOT);
        asm volatile("cp.async.commit_group;" ::: "memory");
    };
    auto storeW = [&](int slot) {
        char* base = smem + slot * STAGE_B + wsto;
        #pragma unroll
        for (int j = 0; j < 8; j++) {
            uint2 u;
            u.x = packh2(wreg[j].x, wreg[j].y);
            u.y = packh2(wreg[j].z, wreg[j].w);
            *(uint2*)(base + j * 8 * 144) = u;         // STS.64, 2-phase clean
        }
    };
    auto compute = [&](int slot) {
        const uint32_t wbase = sb + slot * STAGE_B;
        const uint32_t xbase = wbase + W_TILE_B;
        #pragma unroll
        for (int kk = 0; kk < KT; kk += 16) {
            uint32_t a[2][4], b8[8];
            #pragma unroll
            for (int mt = 0; mt < 2; mt++)
                ldsm4(a[mt], wbase + aoff + (mt * 16 * WSTR + kk) * 2);
            ldsm4(b8,     xbase + boff + kk * 2);                  // n 0..15
            ldsm4(b8 + 4, xbase + boff + 16 * WSTR * 2 + kk * 2);  // n 16..31
            #pragma unroll
            for (int mt = 0; mt < 2; mt++)
                #pragma unroll
                for (int nt = 0; nt < 4; nt++)
                    mma16816(acc[mt][nt], a[mt], b8 + nt * 2);
        }
    };

    // Prologue
    loadW(s0);
    cpX(s0, 0);
    storeW(0);
    asm volatile("cp.async.wait_group 0;" ::: "memory");
    __syncthreads();

    for (int s = s0; s < s1; s++) {
        const int cur = (s - s0) & 1, nxt = cur ^ 1;
        const bool more = (s + 1 < s1);
        if (more) { loadW(s + 1); cpX(s + 1, nxt); }   // gmem in flight under MMAs
        compute(cur);
        if (more) storeW(nxt);
        asm volatile("cp.async.wait_group 0;" ::: "memory");
        __syncthreads();
    }

    // Epilogue: partial[split][o][b], vectorized float2
    float* part = d_partial + (size_t)split * (NOUT * NB);
    #pragma unroll
    for (int mt = 0; mt < 2; mt++)
        #pragma unroll
        for (int nt = 0; nt < 4; nt++) {
            int o  = o_base + warpM * 32 + mt * 16 + (lane >> 2);
            int bb = warpN * 32 + nt * 8 + 2 * (lane & 3);
            *(float2*)&part[(size_t)o * NB + bb] =
                make_float2(acc[mt][nt][0], acc[mt][nt][1]);
            *(float2*)&part[(size_t)(o + 8) * NB + bb] =
                make_float2(acc[mt][nt][2], acc[mt][nt][3]);
        }
}

// --------------------------- reduce ----------------------------------------

__global__ void qa_reduce(const float* __restrict__ bias, float* __restrict__ out) {
    int t = blockIdx.x * blockDim.x + threadIdx.x;  // t = o*64 + b
    int o = t >> 6, b = t & 63;
    float s = bias[o];
    #pragma unroll
    for (int k = 0; k < KS; k++)
        s += d_partial[(size_t)k * (NOUT * NB) + t];   // coalesced reads
    out[(size_t)b * NOUT + o] = s;                     // scattered 4B writes
}

// --------------------------- launch ----------------------------------------

extern "C" void kernel_launch(void* const* d_in, const int* in_sizes, int n_in,
                              void* d_out, int out_size) {
    const float* input_ = (const float*)d_in[0];   // (64,32,32) fp32
    const float* W      = (const float*)d_in[1];   // (1024, 525824) fp32
    const float* bias   = (const float*)d_in[2];   // (1024,) fp32
    float* out = (float*)d_out;                    // (64,32,32) fp32

    cudaFuncSetAttribute(qa_main, cudaFuncAttributeMaxDynamicSharedMemorySize, SMEM_BYTES);

    qa_ij<<<(KTOT + 1023) / 1024, 1024>>>();
    qa_buildXh<<<dim3(KTOT / 256, NB), 256>>>(input_);
    qa_main<<<dim3(MT, KS), 128, SMEM_BYTES>>>(W);
    qa_reduce<<<64, 1024>>>(bias, out);
}

// round 16
// speedup vs baseline: 1.1632x; 1.1031x over previous
#include <cuda_runtime.h>
#include <cuda_fp16.h>
#include <cstdint>

// ---------------------------------------------------------------------------
// QuadraticAttentionModule via fp16 mma.sync.m16n8k16.
//   out[b,o] = bias[o] + sum_k X[b,k] * W[o,k]
//   X[b,k] = xf[b,k] (k<1024) else xf[b,i]*xf[b,j]
// GEMM: M=o(1024), N=b(64), K=525824. X pre-materialized as fp16.
// R16 = R15 mainloop byte-identical. Prep rebuilt table-free:
//   - qa_ij + d_ij (134MB read) deleted; (i,j) runs are contiguous per i.
//   - qa_reduce re-gridded 256x256 (was 64 under-occupied blocks).
// ---------------------------------------------------------------------------

#define IN_DIM 1024
#define NB     64
#define NOUT   1024
#define KTOT   525824
#define KT     64
#define STAGES (KTOT / KT)       // 8216
#define KS     38                // 16*38 = 608 CTAs = 4/SM
#define MT     16                // M tiles of 64
#define SPLIT_Q (STAGES / KS)    // 216
#define SPLIT_R (STAGES % KS)    // 8

#define WSTR     72              // halves per smem row (64 + 8 pad), 144B
#define W_TILE_B (64 * WSTR * 2)    // 9216 B
#define X_TILE_B (64 * WSTR * 2)    // 9216 B
#define STAGE_B  (W_TILE_B + X_TILE_B)   // 18432 B
#define SMEM_BYTES (2 * STAGE_B)         // 36864 B (x4 CTA = 147456)

// Scratch (__device__ globals per allocation rules)
__device__ __align__(16) __half d_Xh[(size_t)NB * KTOT];   // [b][k] fp16 RN
__device__ float  d_partial[(size_t)KS * NOUT * NB];       // [split][o][b]

// --------------------------- PTX helpers ------------------------------------

__device__ __forceinline__ uint32_t smem_u32(const void* p) {
    uint32_t a;
    asm("{ .reg .u64 t; cvta.to.shared.u64 t, %1; cvt.u32.u64 %0, t; }" : "=r"(a) : "l"(p));
    return a;
}
__device__ __forceinline__ void cp16(uint32_t saddr, const void* gptr) {
    asm volatile("cp.async.cg.shared.global [%0], [%1], 16;"
                 :: "r"(saddr), "l"(gptr) : "memory");
}
__device__ __forceinline__ void ldsm4(uint32_t* r, uint32_t addr) {
    asm volatile("ldmatrix.sync.aligned.m8n8.x4.shared.b16 {%0,%1,%2,%3}, [%4];"
                 : "=r"(r[0]), "=r"(r[1]), "=r"(r[2]), "=r"(r[3]) : "r"(addr));
}
__device__ __forceinline__ void mma16816(float* d, const uint32_t* a, const uint32_t* b) {
    asm volatile(
        "mma.sync.aligned.m16n8k16.row.col.f32.f16.f16.f32 "
        "{%0,%1,%2,%3}, {%4,%5,%6,%7}, {%8,%9}, {%0,%1,%2,%3};\n"
        : "+f"(d[0]), "+f"(d[1]), "+f"(d[2]), "+f"(d[3])
        : "r"(a[0]), "r"(a[1]), "r"(a[2]), "r"(a[3]), "r"(b[0]), "r"(b[1]));
}
// Pack two fp32 -> one u32 of two rn-rounded fp16 (lo = a, hi = b).
__device__ __forceinline__ uint32_t packh2(float a, float b) {
    uint32_t r;
    asm("cvt.rn.f16x2.f32 %0, %2, %1;" : "=r"(r) : "f"(a), "f"(b));
    return r;
}
// Streaming (evict-first) 16B load for the zero-reuse W operand.
__device__ __forceinline__ float4 ldg_cs4(const float4* p) {
    float4 v;
    asm volatile("ld.global.cs.v4.f32 {%0,%1,%2,%3}, [%4];"
                 : "=f"(v.x), "=f"(v.y), "=f"(v.z), "=f"(v.w) : "l"(p));
    return v;
}

// --------------------------- prep kernels (table-free) ----------------------

// Linear part: X[b][k] = xf[b][k], k < 1024.
__global__ void qa_buildX_lin(const float* __restrict__ in) {
    int b = blockIdx.x, k = threadIdx.x;           // grid 64, block 1024
    d_Xh[(size_t)b * KTOT + k] = __float2half_rn(in[b * IN_DIM + k]);
}

// Quadratic part: for fixed i, k = 1024 + triu_off(i) + (j - i), j = i..1023
// is a contiguous run. triu_off(i) = i*1024 - i*(i-1)/2.
__global__ void qa_buildX_quad(const float* __restrict__ in) {
    const int i = blockIdx.x, b = blockIdx.y;      // grid (1024, 64), block 256
    const long long base = (long long)IN_DIM
                         + (long long)i * IN_DIM - (long long)i * (i - 1) / 2
                         - (long long)i;           // + j gives k
    const float xi = in[b * IN_DIM + i];
    const float* row = in + b * IN_DIM;
    __half* dst = d_Xh + (size_t)b * KTOT + base;
    for (int j = i + threadIdx.x; j < IN_DIM; j += blockDim.x)
        dst[j] = __float2half_rn(xi * row[j]);     // coalesced 2B writes
}

// --------------------------- main GEMM -------------------------------------
// CTA tile 64(M) x 64(N) x KT=64. 4 warps as 2(M,32) x 2(N,32).
// Per slot: W [64][72] halves, X [64][72] halves (rows padded to 144B).

__global__ __launch_bounds__(128, 4)
void qa_main(const float* __restrict__ W) {
    extern __shared__ __align__(128) char smem[];
    const uint32_t sb = smem_u32(smem);
    const int tid = threadIdx.x, lane = tid & 31, wid = tid >> 5;
    const int warpM = wid >> 1, warpN = wid & 1;

    const int o_base = blockIdx.x * 64;
    const int split  = blockIdx.y;
    const int s0 = split * SPLIT_Q + min(split, SPLIT_R);
    const int s1 = s0 + SPLIT_Q + (split < SPLIT_R ? 1 : 0);

    // --- W producer: step j=0..7 -> row (tid>>4)+8j, 16B chunk tid&15.
    const int wr0 = tid >> 4, wc = tid & 15;
    const float* wptr = W + (size_t)(o_base + wr0) * KTOT + (size_t)s0 * KT + wc * 4;
    const uint32_t wsto = wr0 * 144 + wc * 8;          // fp16 dst (+j*8*144)

    // --- X producer: step j=0..3 -> row (tid>>3)+16j, 16B chunk tid&7.
    const int xr0 = tid >> 3, xc = tid & 7;
    const __half* xptr = d_Xh + (size_t)xr0 * KTOT + (size_t)s0 * KT + xc * 8;
    const uint32_t xsto = xr0 * 144 + xc * 16;         // (+j*16*144)

    // Fragment base byte offsets within slot (ldmatrix address schemes)
    const uint32_t aoff = ((warpM * 32 + (lane & 15)) * WSTR + ((lane >> 4) * 8)) * 2;
    const uint32_t boff = ((warpN * 32 + ((lane >> 4) * 8) + (lane & 7)) * WSTR
                          + (((lane >> 3) & 1) * 8)) * 2;

    float4 wreg[8];
    float  acc[2][4][4];
    #pragma unroll
    for (int mt = 0; mt < 2; mt++)
        #pragma unroll
        for (int nt = 0; nt < 4; nt++)
            #pragma unroll
            for (int r = 0; r < 4; r++) acc[mt][nt][r] = 0.f;

    auto loadW = [&](int s) {
        const float* p = wptr + (size_t)(s - s0) * KT;
        #pragma unroll
        for (int j = 0; j < 8; j++)
            wreg[j] = ldg_cs4((const float4*)(p + (size_t)(8 * j) * KTOT));
    };
    auto cpX = [&](int s, int slot) {
        uint32_t dst = sb + slot * STAGE_B + W_TILE_B + xsto;
        const __half* p = xptr + (size_t)(s - s0) * KT;
        #pragma unroll
        for (int j = 0; j < 4; j++)
            cp16(dst + j * 16 * 144, p + (size_t)(16 * j) * KTOT);
        asm volatile("cp.async.commit_group;" ::: "memory");
    };
    auto storeW = [&](int slot) {
        char* base = smem + slot * STAGE_B + wsto;
        #pragma unroll
        for (int j = 0; j < 8; j++) {
            uint2 u;
            u.x = packh2(wreg[j].x, wreg[j].y);
            u.y = packh2(wreg[j].z, wreg[j].w);
            *(uint2*)(base + j * 8 * 144) = u;         // STS.64, 2-phase clean
        }
    };
    auto compute = [&](int slot) {
        const uint32_t wbase = sb + slot * STAGE_B;
        const uint32_t xbase = wbase + W_TILE_B;
        #pragma unroll
        for (int kk = 0; kk < KT; kk += 16) {
            uint32_t a[2][4], b8[8];
            #pragma unroll
            for (int mt = 0; mt < 2; mt++)
                ldsm4(a[mt], wbase + aoff + (mt * 16 * WSTR + kk) * 2);
            ldsm4(b8,     xbase + boff + kk * 2);                  // n 0..15
            ldsm4(b8 + 4, xbase + boff + 16 * WSTR * 2 + kk * 2);  // n 16..31
            #pragma unroll
            for (int mt = 0; mt < 2; mt++)
                #pragma unroll
                for (int nt = 0; nt < 4; nt++)
                    mma16816(acc[mt][nt], a[mt], b8 + nt * 2);
        }
    };

    // Prologue
    loadW(s0);
    cpX(s0, 0);
    storeW(0);
    asm volatile("cp.async.wait_group 0;" ::: "memory");
    __syncthreads();

    for (int s = s0; s < s1; s++) {
        const int cur = (s - s0) & 1, nxt = cur ^ 1;
        const bool more = (s + 1 < s1);
        if (more) { loadW(s + 1); cpX(s + 1, nxt); }   // gmem in flight under MMAs
        compute(cur);
        if (more) storeW(nxt);
        asm volatile("cp.async.wait_group 0;" ::: "memory");
        __syncthreads();
    }

    // Epilogue: partial[split][o][b], vectorized float2
    float* part = d_partial + (size_t)split * (NOUT * NB);
    #pragma unroll
    for (int mt = 0; mt < 2; mt++)
        #pragma unroll
        for (int nt = 0; nt < 4; nt++) {
            int o  = o_base + warpM * 32 + mt * 16 + (lane >> 2);
            int bb = warpN * 32 + nt * 8 + 2 * (lane & 3);
            *(float2*)&part[(size_t)o * NB + bb] =
                make_float2(acc[mt][nt][0], acc[mt][nt][1]);
            *(float2*)&part[(size_t)(o + 8) * NB + bb] =
                make_float2(acc[mt][nt][2], acc[mt][nt][3]);
        }
}

// --------------------------- reduce ----------------------------------------

__global__ void qa_reduce(const float* __restrict__ bias, float* __restrict__ out) {
    int t = blockIdx.x * blockDim.x + threadIdx.x;  // t = o*64 + b (grid 256x256)
    int o = t >> 6, b = t & 63;
    float s = bias[o];
    #pragma unroll
    for (int k = 0; k < KS; k++)
        s += d_partial[(size_t)k * (NOUT * NB) + t];   // coalesced reads
    out[(size_t)b * NOUT + o] = s;                     // scattered 4B writes
}

// --------------------------- launch ----------------------------------------

extern "C" void kernel_launch(void* const* d_in, const int* in_sizes, int n_in,
                              void* d_out, int out_size) {
    const float* input_ = (const float*)d_in[0];   // (64,32,32) fp32
    const float* W      = (const float*)d_in[1];   // (1024, 525824) fp32
    const float* bias   = (const float*)d_in[2];   // (1024,) fp32
    float* out = (float*)d_out;                    // (64,32,32) fp32

    cudaFuncSetAttribute(qa_main, cudaFuncAttributeMaxDynamicSharedMemorySize, SMEM_BYTES);

    qa_buildX_lin<<<64, 1024>>>(input_);
    qa_buildX_quad<<<dim3(IN_DIM, NB), 256>>>(input_);
    qa_main<<<dim3(MT, KS), 128, SMEM_BYTES>>>(W);
    qa_reduce<<<256, 256>>>(bias, out);
}